// round 3
// baseline (speedup 1.0000x reference)
#include <cuda_runtime.h>
#include <math.h>

// Problem constants (fixed by the dataset)
#define T_TOK 1024
#define H_DIM 2048
#define I_DIM 1408
#define N_EXP 8
#define TOPK  2

#define BM 64
#define BN 64
#define BK 16

// Padded slot space: each expert's token list padded to a multiple of BM.
// max = 2048 + 8*63 = 2552, rounded into 64-multiples -> <= 2496; allocate 2560.
#define MAXSLOT  2560
#define MAXTILES 40

// -------- scratch (static device arrays; no allocations allowed) --------
__device__ int   g_token_of_slot[MAXSLOT];
__device__ float g_slot_weight[MAXSLOT];
__device__ int   g_tile_expert[MAXTILES];
__device__ int   g_num_tiles;
__device__ float g_act[(size_t)MAXSLOT * I_DIM];   // SiLU(gate)*up activations, ~14.4 MB

// ============================================================
// Routing: softmax -> top2 -> renormalize; build padded per-expert slot lists.
// Single block, 1024 threads (one per token).
// ============================================================
__global__ void routing_kernel(const float* __restrict__ logits) {
    __shared__ int s_cnt[N_EXP];
    __shared__ int s_cur[N_EXP];
    __shared__ int s_off[N_EXP + 1];

    const int t = threadIdx.x;
    if (t < N_EXP) { s_cnt[t] = 0; s_cur[t] = 0; }

    // init all slots to invalid (pad marker)
    for (int s = t; s < MAXSLOT; s += blockDim.x) g_token_of_slot[s] = -1;
    __syncthreads();

    int e1 = 0, e2 = 0;
    float w1 = 0.f, w2 = 0.f;
    if (t < T_TOK) {
        float l[N_EXP];
#pragma unroll
        for (int e = 0; e < N_EXP; e++) l[e] = logits[t * N_EXP + e];
        float b1 = -1e30f;
#pragma unroll
        for (int e = 0; e < N_EXP; e++) if (l[e] > b1) { b1 = l[e]; e1 = e; }
        float b2 = -1e30f;
        e2 = (e1 == 0) ? 1 : 0;
#pragma unroll
        for (int e = 0; e < N_EXP; e++) if (e != e1 && l[e] > b2) { b2 = l[e]; e2 = e; }
        // softmax denominator cancels under top-2 renormalization:
        float p2 = expf(b2 - b1);           // exp(l2)/exp(l1)
        w1 = 1.f / (1.f + p2);
        w2 = p2 / (1.f + p2);
        atomicAdd(&s_cnt[e1], 1);
        atomicAdd(&s_cnt[e2], 1);
    }
    __syncthreads();

    if (t == 0) {
        int off = 0;
#pragma unroll
        for (int e = 0; e < N_EXP; e++) {
            s_off[e] = off;
            int tiles = (s_cnt[e] + BM - 1) / BM;
            for (int i = 0; i < tiles; i++) g_tile_expert[off / BM + i] = e;
            off += tiles * BM;
        }
        s_off[N_EXP] = off;
        g_num_tiles = off / BM;
    }
    __syncthreads();

    if (t < T_TOK) {
        int p = atomicAdd(&s_cur[e1], 1);
        int s = s_off[e1] + p;
        g_token_of_slot[s] = t;
        g_slot_weight[s]   = w1;
        p = atomicAdd(&s_cur[e2], 1);
        s = s_off[e2] + p;
        g_token_of_slot[s] = t;
        g_slot_weight[s]   = w2;
    }
}

// ============================================================
// GEMM1 + SiLU*up:
//   act[slot, n] = silu(x[t] . w1[e,n,:]) * (x[t] . w3[e,n,:])
// w13 layout: [E, 2I, H]; gate rows [0,I), up rows [I,2I).
// Block: 64 (slots) x 64 (I cols), K-loop over H=2048.
// ============================================================
__global__ __launch_bounds__(256) void gemm1_silu(const float* __restrict__ x,
                                                  const float* __restrict__ w13) {
    const int tile_m = blockIdx.x;
    if (tile_m >= g_num_tiles) return;
    const int e     = g_tile_expert[tile_m];
    const int nbase = blockIdx.y * BN;

    __shared__ float As[BK][BM + 4];   // row stride 68 floats = 272B (16B aligned)
    __shared__ float Bg[BK][BN + 4];
    __shared__ float Bu[BK][BN + 4];

    const int tid = threadIdx.x;
    const int lm  = tid >> 2;           // 0..63
    const int lk  = (tid & 3) * 4;      // 0,4,8,12
    const int ty  = tid >> 4;           // 0..15 (m quads)
    const int tx  = tid & 15;           // 0..15 (n quads)

    const int tok = g_token_of_slot[tile_m * BM + lm];
    const float* arow  = x + (size_t)(tok < 0 ? 0 : tok) * H_DIM;
    const float* bgrow = w13 + ((size_t)e * 2 * I_DIM + (nbase + lm)) * H_DIM;
    const float* burow = w13 + ((size_t)e * 2 * I_DIM + I_DIM + (nbase + lm)) * H_DIM;

    float acc_g[4][4], acc_u[4][4];
#pragma unroll
    for (int i = 0; i < 4; i++)
#pragma unroll
        for (int j = 0; j < 4; j++) { acc_g[i][j] = 0.f; acc_u[i][j] = 0.f; }

#pragma unroll 1
    for (int k0 = 0; k0 < H_DIM; k0 += BK) {
        float4 av = (tok >= 0) ? *(const float4*)(arow + k0 + lk)
                               : make_float4(0.f, 0.f, 0.f, 0.f);
        float4 bgv = *(const float4*)(bgrow + k0 + lk);
        float4 buv = *(const float4*)(burow + k0 + lk);
        As[lk + 0][lm] = av.x;  As[lk + 1][lm] = av.y;
        As[lk + 2][lm] = av.z;  As[lk + 3][lm] = av.w;
        Bg[lk + 0][lm] = bgv.x; Bg[lk + 1][lm] = bgv.y;
        Bg[lk + 2][lm] = bgv.z; Bg[lk + 3][lm] = bgv.w;
        Bu[lk + 0][lm] = buv.x; Bu[lk + 1][lm] = buv.y;
        Bu[lk + 2][lm] = buv.z; Bu[lk + 3][lm] = buv.w;
        __syncthreads();

#pragma unroll
        for (int kk = 0; kk < BK; kk++) {
            const float4 a  = *(const float4*)&As[kk][ty * 4];
            const float4 bg = *(const float4*)&Bg[kk][tx * 4];
            const float4 bu = *(const float4*)&Bu[kk][tx * 4];
            const float avr[4]  = { a.x,  a.y,  a.z,  a.w };
            const float bgr[4]  = { bg.x, bg.y, bg.z, bg.w };
            const float bur[4]  = { bu.x, bu.y, bu.z, bu.w };
#pragma unroll
            for (int i = 0; i < 4; i++)
#pragma unroll
                for (int j = 0; j < 4; j++) {
                    acc_g[i][j] = fmaf(avr[i], bgr[j], acc_g[i][j]);
                    acc_u[i][j] = fmaf(avr[i], bur[j], acc_u[i][j]);
                }
        }
        __syncthreads();
    }

    const int mbase = tile_m * BM + ty * 4;
#pragma unroll
    for (int i = 0; i < 4; i++) {
        const int slot = mbase + i;
        if (g_token_of_slot[slot] >= 0) {
            float* dst = g_act + (size_t)slot * I_DIM + nbase + tx * 4;
#pragma unroll
            for (int j = 0; j < 4; j++) {
                float g = acc_g[i][j];
                float u = acc_u[i][j];
                dst[j] = u * g / (1.f + expf(-g));
            }
        }
    }
}

// ============================================================
// GEMM2 + weighted scatter:
//   out[t, h] += w_slot * (act[slot] . w2[e,h,:])
// w2 layout: [E, H, I]. K-loop over I=1408.
// Each token appears in exactly 2 slots -> 2 commutative fp32 atomic adds.
// ============================================================
__global__ __launch_bounds__(256) void gemm2_scatter(const float* __restrict__ w2,
                                                     float* __restrict__ out) {
    const int tile_m = blockIdx.x;
    if (tile_m >= g_num_tiles) return;
    const int e     = g_tile_expert[tile_m];
    const int nbase = blockIdx.y * BN;   // over H

    __shared__ float As[BK][BM + 4];
    __shared__ float Bs[BK][BN + 4];

    const int tid = threadIdx.x;
    const int lm  = tid >> 2;
    const int lk  = (tid & 3) * 4;
    const int ty  = tid >> 4;
    const int tx  = tid & 15;

    const int slot_l = tile_m * BM + lm;
    const float* arow = g_act + (size_t)slot_l * I_DIM;
    const float* brow = w2 + ((size_t)e * H_DIM + (nbase + lm)) * I_DIM;
    const int tok_l = g_token_of_slot[slot_l];

    float acc[4][4];
#pragma unroll
    for (int i = 0; i < 4; i++)
#pragma unroll
        for (int j = 0; j < 4; j++) acc[i][j] = 0.f;

#pragma unroll 1
    for (int k0 = 0; k0 < I_DIM; k0 += BK) {
        float4 av = (tok_l >= 0) ? *(const float4*)(arow + k0 + lk)
                                 : make_float4(0.f, 0.f, 0.f, 0.f);
        float4 bv = *(const float4*)(brow + k0 + lk);
        As[lk + 0][lm] = av.x; As[lk + 1][lm] = av.y;
        As[lk + 2][lm] = av.z; As[lk + 3][lm] = av.w;
        Bs[lk + 0][lm] = bv.x; Bs[lk + 1][lm] = bv.y;
        Bs[lk + 2][lm] = bv.z; Bs[lk + 3][lm] = bv.w;
        __syncthreads();

#pragma unroll
        for (int kk = 0; kk < BK; kk++) {
            const float4 a = *(const float4*)&As[kk][ty * 4];
            const float4 b = *(const float4*)&Bs[kk][tx * 4];
            const float ar[4] = { a.x, a.y, a.z, a.w };
            const float br[4] = { b.x, b.y, b.z, b.w };
#pragma unroll
            for (int i = 0; i < 4; i++)
#pragma unroll
                for (int j = 0; j < 4; j++)
                    acc[i][j] = fmaf(ar[i], br[j], acc[i][j]);
        }
        __syncthreads();
    }

    const int mbase = tile_m * BM + ty * 4;
#pragma unroll
    for (int i = 0; i < 4; i++) {
        const int slot = mbase + i;
        const int tok  = g_token_of_slot[slot];
        if (tok >= 0) {
            const float w = g_slot_weight[slot];
            float* dst = out + (size_t)tok * H_DIM + nbase + tx * 4;
#pragma unroll
            for (int j = 0; j < 4; j++)
                atomicAdd(&dst[j], w * acc[i][j]);
        }
    }
}

// ============================================================
extern "C" void kernel_launch(void* const* d_in, const int* in_sizes, int n_in,
                              void* d_out, int out_size) {
    const float* x      = (const float*)d_in[0];   // [1024, 2048]
    const float* logits = (const float*)d_in[1];   // [1024, 8]
    const float* w13    = (const float*)d_in[2];   // [8, 2816, 2048]
    const float* w2     = (const float*)d_in[3];   // [8, 2048, 1408]
    float* out = (float*)d_out;                    // [1024, 2048]
    (void)in_sizes; (void)n_in;

    cudaMemsetAsync(d_out, 0, (size_t)out_size * sizeof(float));
    routing_kernel<<<1, 1024>>>(logits);
    gemm1_silu<<<dim3(MAXTILES, I_DIM / BN), 256>>>(x, w13);
    gemm2_scatter<<<dim3(MAXTILES, H_DIM / BN), 256>>>(w2, out);
}

// round 5
// speedup vs baseline: 1.7411x; 1.7411x over previous
#include <cuda_runtime.h>
#include <cstdint>
#include <math.h>

// ---------------- problem constants ----------------
#define T_TOK 1024
#define H_DIM 2048
#define I_DIM 1408
#define N_EXP 8

// ---------------- tiling ----------------
#define BM 128
#define BN 128
#define BK 32
#define MAXSLOT  3072     // sum ceil(cnt_e/128)*128 <= 2048 + 8*128 = 3072
#define MAXTILES 24

#define SM_STRIDE 36      // floats per smem row (144 B, 16B-aligned, conflict-free frags)
#define TILE_WORDS (BM * SM_STRIDE)                 // 4608 floats = 18 KB
#define SMEM_DYN_BYTES (4 * TILE_WORDS * 4)         // A0,A1,B0,B1 = 72 KB

// ---------------- scratch ----------------
__device__ int   g_token_of_slot[MAXSLOT];
__device__ float g_slot_weight[MAXSLOT];
__device__ int   g_tile_expert[MAXTILES];
__device__ int   g_num_tiles;
__device__ float g_act[(size_t)MAXSLOT * I_DIM];   // ~17.3 MB

// ---------------- PTX helpers (baseline sm_80+ only; no 'a'-gated features) ----
__device__ __forceinline__ uint32_t smem_u32(const void* p) {
    uint32_t a;
    asm("{ .reg .u64 t; cvta.to.shared.u64 t, %1; cvt.u32.u64 %0, t; }" : "=r"(a) : "l"(p));
    return a;
}
#define CP_ASYNC16(dst_u32, src_ptr) \
    asm volatile("cp.async.cg.shared.global [%0], [%1], 16;" :: "r"(dst_u32), "l"(src_ptr))
#define CP_COMMIT()  asm volatile("cp.async.commit_group;" ::: "memory")
#define CP_WAIT(N)   asm volatile("cp.async.wait_group %0;" :: "n"(N) : "memory")

__device__ __forceinline__ uint32_t f2tf32(float f) {
    uint32_t r;
    asm("cvt.rna.tf32.f32 %0, %1;" : "=r"(r) : "f"(f));
    return r;
}
__device__ __forceinline__ void mma_tf32(float* c, const uint32_t* a, const uint32_t* b) {
    asm volatile(
        "mma.sync.aligned.m16n8k8.row.col.f32.tf32.tf32.f32 "
        "{%0,%1,%2,%3}, {%4,%5,%6,%7}, {%8,%9}, {%0,%1,%2,%3};"
        : "+f"(c[0]), "+f"(c[1]), "+f"(c[2]), "+f"(c[3])
        : "r"(a[0]), "r"(a[1]), "r"(a[2]), "r"(a[3]), "r"(b[0]), "r"(b[1]));
}

// ============================================================
// Routing: softmax -> top2 -> renormalize; padded per-expert slot lists (x128).
// ============================================================
__global__ void routing_kernel(const float* __restrict__ logits) {
    __shared__ int s_cnt[N_EXP];
    __shared__ int s_cur[N_EXP];
    __shared__ int s_off[N_EXP + 1];

    const int t = threadIdx.x;
    if (t < N_EXP) { s_cnt[t] = 0; s_cur[t] = 0; }
    for (int s = t; s < MAXSLOT; s += blockDim.x) g_token_of_slot[s] = -1;
    __syncthreads();

    int e1 = 0, e2 = 0;
    float w1 = 0.f, w2 = 0.f;
    if (t < T_TOK) {
        float l[N_EXP];
#pragma unroll
        for (int e = 0; e < N_EXP; e++) l[e] = logits[t * N_EXP + e];
        float b1 = -1e30f;
#pragma unroll
        for (int e = 0; e < N_EXP; e++) if (l[e] > b1) { b1 = l[e]; e1 = e; }
        float b2 = -1e30f;
        e2 = (e1 == 0) ? 1 : 0;
#pragma unroll
        for (int e = 0; e < N_EXP; e++) if (e != e1 && l[e] > b2) { b2 = l[e]; e2 = e; }
        float p2 = expf(b2 - b1);
        w1 = 1.f / (1.f + p2);
        w2 = p2 / (1.f + p2);
        atomicAdd(&s_cnt[e1], 1);
        atomicAdd(&s_cnt[e2], 1);
    }
    __syncthreads();

    if (t == 0) {
        int off = 0;
        for (int e = 0; e < N_EXP; e++) {
            s_off[e] = off;
            int tiles = (s_cnt[e] + BM - 1) / BM;
            for (int i = 0; i < tiles; i++) g_tile_expert[off / BM + i] = e;
            off += tiles * BM;
        }
        s_off[N_EXP] = off;
        g_num_tiles = off / BM;
    }
    __syncthreads();

    if (t < T_TOK) {
        int p = atomicAdd(&s_cur[e1], 1);
        int s = s_off[e1] + p;
        g_token_of_slot[s] = t;
        g_slot_weight[s]   = w1;
        p = atomicAdd(&s_cur[e2], 1);
        s = s_off[e2] + p;
        g_token_of_slot[s] = t;
        g_slot_weight[s]   = w2;
    }
}

// ============================================================
// Common MMA mainloop (A: 128 x BK slots-rows, B: 128 x BK n-rows).
// Warp grid 2(m) x 4(n); warp tile 64x32; fragments per PTX m16n8k8 tf32 layout.
// Accumulators acc[mf][nf][4].
// ============================================================
struct FragCtx {
    int wm, wn, g, tg;
};

__device__ __forceinline__ void mma_chunk(const float* __restrict__ A,
                                          const float* __restrict__ B,
                                          const FragCtx& f,
                                          float acc[4][4][4]) {
#pragma unroll
    for (int ks = 0; ks < 4; ks++) {
        uint32_t af[4][4];
#pragma unroll
        for (int mf = 0; mf < 4; mf++) {
            const int row = f.wm * 64 + mf * 16 + f.g;
            const int base = row * SM_STRIDE + ks * 8 + f.tg;
            af[mf][0] = f2tf32(A[base]);
            af[mf][1] = f2tf32(A[base + 8 * SM_STRIDE]);
            af[mf][2] = f2tf32(A[base + 4]);
            af[mf][3] = f2tf32(A[base + 8 * SM_STRIDE + 4]);
        }
        uint32_t bf[4][2];
#pragma unroll
        for (int nf = 0; nf < 4; nf++) {
            const int n = f.wn * 32 + nf * 8 + f.g;
            const int base = n * SM_STRIDE + ks * 8 + f.tg;
            bf[nf][0] = f2tf32(B[base]);
            bf[nf][1] = f2tf32(B[base + 4]);
        }
#pragma unroll
        for (int mf = 0; mf < 4; mf++)
#pragma unroll
            for (int nf = 0; nf < 4; nf++)
                mma_tf32(acc[mf][nf], af[mf], bf[nf]);
    }
}

// ============================================================
// GEMM1 + SiLU*up. B columns interleaved: smem B row 2j = gate(nbJ+j), 2j+1 = up(nbJ+j).
// Output per thread: c0/c1 = gate/up of same j. grid = (MAXTILES, I/64)
// ============================================================
__global__ __launch_bounds__(256)
void gemm1_mma(const float* __restrict__ x, const float* __restrict__ w13) {
    const int tile_m = blockIdx.x;
    if (tile_m >= g_num_tiles) return;
    const int e   = g_tile_expert[tile_m];
    const int nbJ = blockIdx.y * 64;

    extern __shared__ float sm[];
    float* Abuf[2] = { sm,                  sm + TILE_WORDS };
    float* Bbuf[2] = { sm + 2 * TILE_WORDS, sm + 3 * TILE_WORDS };

    const int tid = threadIdx.x;
    const int wid = tid >> 5, lid = tid & 31;
    FragCtx f = { wid & 1, wid >> 1, lid >> 2, lid & 3 };

    // loader assignment: row r = tid>>1 (0..127), 4x16B segments sb..sb+3
    const int r  = tid >> 1;
    const int sb = (tid & 1) * 4;
    const int tokr = g_token_of_slot[tile_m * BM + r];
    const float* aSrc = x + (size_t)(tokr < 0 ? 0 : tokr) * H_DIM;
    const int j = r >> 1;
    const int wrow = (r & 1) ? (I_DIM + nbJ + j) : (nbJ + j);
    const float* bSrc = w13 + ((size_t)e * 2 * I_DIM + wrow) * H_DIM;

    const uint32_t aDst = smem_u32(Abuf[0]) + r * (SM_STRIDE * 4) + sb * 16;
    const uint32_t bDst = smem_u32(Bbuf[0]) + r * (SM_STRIDE * 4) + sb * 16;
    const uint32_t bufStep = TILE_WORDS * 4;

    float acc[4][4][4];
#pragma unroll
    for (int a = 0; a < 4; a++)
#pragma unroll
        for (int b = 0; b < 4; b++)
#pragma unroll
            for (int c = 0; c < 4; c++) acc[a][b][c] = 0.f;

    const int NC = H_DIM / BK;   // 64
    // prologue
#pragma unroll
    for (int i = 0; i < 4; i++) {
        CP_ASYNC16(aDst + i * 16, aSrc + (sb + i) * 4);
        CP_ASYNC16(bDst + i * 16, bSrc + (sb + i) * 4);
    }
    CP_COMMIT();

#pragma unroll 1
    for (int c = 0; c < NC; c++) {
        const int buf = c & 1;
        if (c + 1 < NC) {
            const int pb = buf ^ 1;
            const int k1 = (c + 1) * BK;
#pragma unroll
            for (int i = 0; i < 4; i++) {
                CP_ASYNC16(aDst + pb * bufStep + i * 16, aSrc + k1 + (sb + i) * 4);
                CP_ASYNC16(bDst + pb * bufStep + i * 16, bSrc + k1 + (sb + i) * 4);
            }
            CP_COMMIT();
            CP_WAIT(1);
        } else {
            CP_WAIT(0);
        }
        __syncthreads();
        mma_chunk(Abuf[buf], Bbuf[buf], f, acc);
        __syncthreads();
    }

    // epilogue: silu(gate)*up
#pragma unroll
    for (int mf = 0; mf < 4; mf++) {
#pragma unroll
        for (int half = 0; half < 2; half++) {
            const int slot = tile_m * BM + f.wm * 64 + mf * 16 + f.g + half * 8;
            if (g_token_of_slot[slot] >= 0) {
                float* dst = g_act + (size_t)slot * I_DIM + nbJ;
#pragma unroll
                for (int nf = 0; nf < 4; nf++) {
                    const int jj = f.wn * 16 + nf * 4 + f.tg;
                    const float gt = acc[mf][nf][half * 2 + 0];
                    const float up = acc[mf][nf][half * 2 + 1];
                    dst[jj] = up * gt / (1.f + expf(-gt));
                }
            }
        }
    }
}

// ============================================================
// GEMM2 + weighted atomic scatter. grid = (MAXTILES, H/128)
// ============================================================
__global__ __launch_bounds__(256)
void gemm2_mma(const float* __restrict__ w2, float* __restrict__ out) {
    const int tile_m = blockIdx.x;
    if (tile_m >= g_num_tiles) return;
    const int e     = g_tile_expert[tile_m];
    const int nbase = blockIdx.y * BN;

    extern __shared__ float sm[];
    float* Abuf[2] = { sm,                  sm + TILE_WORDS };
    float* Bbuf[2] = { sm + 2 * TILE_WORDS, sm + 3 * TILE_WORDS };

    const int tid = threadIdx.x;
    const int wid = tid >> 5, lid = tid & 31;
    FragCtx f = { wid & 1, wid >> 1, lid >> 2, lid & 3 };

    const int r  = tid >> 1;
    const int sb = (tid & 1) * 4;
    const float* aSrc = g_act + (size_t)(tile_m * BM + r) * I_DIM;  // stale pad rows only pollute dropped C rows
    const float* bSrc = w2 + ((size_t)e * H_DIM + (nbase + r)) * I_DIM;

    const uint32_t aDst = smem_u32(Abuf[0]) + r * (SM_STRIDE * 4) + sb * 16;
    const uint32_t bDst = smem_u32(Bbuf[0]) + r * (SM_STRIDE * 4) + sb * 16;
    const uint32_t bufStep = TILE_WORDS * 4;

    float acc[4][4][4];
#pragma unroll
    for (int a = 0; a < 4; a++)
#pragma unroll
        for (int b = 0; b < 4; b++)
#pragma unroll
            for (int c = 0; c < 4; c++) acc[a][b][c] = 0.f;

    const int NC = I_DIM / BK;   // 44
#pragma unroll
    for (int i = 0; i < 4; i++) {
        CP_ASYNC16(aDst + i * 16, aSrc + (sb + i) * 4);
        CP_ASYNC16(bDst + i * 16, bSrc + (sb + i) * 4);
    }
    CP_COMMIT();

#pragma unroll 1
    for (int c = 0; c < NC; c++) {
        const int buf = c & 1;
        if (c + 1 < NC) {
            const int pb = buf ^ 1;
            const int k1 = (c + 1) * BK;
#pragma unroll
            for (int i = 0; i < 4; i++) {
                CP_ASYNC16(aDst + pb * bufStep + i * 16, aSrc + k1 + (sb + i) * 4);
                CP_ASYNC16(bDst + pb * bufStep + i * 16, bSrc + k1 + (sb + i) * 4);
            }
            CP_COMMIT();
            CP_WAIT(1);
        } else {
            CP_WAIT(0);
        }
        __syncthreads();
        mma_chunk(Abuf[buf], Bbuf[buf], f, acc);
        __syncthreads();
    }

#pragma unroll
    for (int mf = 0; mf < 4; mf++) {
#pragma unroll
        for (int half = 0; half < 2; half++) {
            const int slot = tile_m * BM + f.wm * 64 + mf * 16 + f.g + half * 8;
            const int tok  = g_token_of_slot[slot];
            if (tok >= 0) {
                const float w = g_slot_weight[slot];
                float* dst = out + (size_t)tok * H_DIM + nbase;
#pragma unroll
                for (int nf = 0; nf < 4; nf++) {
                    const int col = f.wn * 32 + nf * 8 + f.tg * 2;
                    atomicAdd(&dst[col],     w * acc[mf][nf][half * 2 + 0]);
                    atomicAdd(&dst[col + 1], w * acc[mf][nf][half * 2 + 1]);
                }
            }
        }
    }
}

// ============================================================
extern "C" void kernel_launch(void* const* d_in, const int* in_sizes, int n_in,
                              void* d_out, int out_size) {
    const float* x      = (const float*)d_in[0];   // [1024, 2048]
    const float* logits = (const float*)d_in[1];   // [1024, 8]
    const float* w13    = (const float*)d_in[2];   // [8, 2816, 2048]
    const float* w2     = (const float*)d_in[3];   // [8, 2048, 1408]
    float* out = (float*)d_out;                    // [1024, 2048]
    (void)in_sizes; (void)n_in;

    cudaFuncSetAttribute(gemm1_mma, cudaFuncAttributeMaxDynamicSharedMemorySize, SMEM_DYN_BYTES);
    cudaFuncSetAttribute(gemm2_mma, cudaFuncAttributeMaxDynamicSharedMemorySize, SMEM_DYN_BYTES);

    cudaMemsetAsync(d_out, 0, (size_t)out_size * sizeof(float));
    routing_kernel<<<1, 1024>>>(logits);
    gemm1_mma<<<dim3(MAXTILES, I_DIM / 64), 256, SMEM_DYN_BYTES>>>(x, w13);
    gemm2_mma<<<dim3(MAXTILES, H_DIM / BN), 256, SMEM_DYN_BYTES>>>(w2, out);
}

// round 6
// speedup vs baseline: 1.9197x; 1.1026x over previous
#include <cuda_runtime.h>
#include <cstdint>
#include <math.h>

// ---------------- problem constants ----------------
#define T_TOK 1024
#define H_DIM 2048
#define I_DIM 1408
#define N_EXP 8

// ---------------- tiling ----------------
#define BM 128
#define BN 128
#define BK 32
#define NSTAGE 3
#define MAXSLOT  3072
#define MAXTILES 24

#define SM_STRIDE 36      // floats per smem row (144 B; frag banks (4g+tg)%32 all distinct)
#define TILE_WORDS (BM * SM_STRIDE)                     // 4608 floats = 18 KB
#define SMEM_DYN_BYTES (2 * NSTAGE * TILE_WORDS * 4)    // 3 stages x (A+B) = 108 KB

// ---------------- scratch ----------------
__device__ int   g_token_of_slot[MAXSLOT];
__device__ float g_slot_weight[MAXSLOT];
__device__ int   g_tile_expert[MAXTILES];
__device__ int   g_num_tiles;
__device__ float g_act[(size_t)MAXSLOT * I_DIM];   // ~17.3 MB

// ---------------- PTX helpers (baseline sm_80+; nothing 'a'-gated) ----------------
__device__ __forceinline__ uint32_t smem_u32(const void* p) {
    uint32_t a;
    asm("{ .reg .u64 t; cvta.to.shared.u64 t, %1; cvt.u32.u64 %0, t; }" : "=r"(a) : "l"(p));
    return a;
}
#define CP_ASYNC16(dst_u32, src_ptr) \
    asm volatile("cp.async.cg.shared.global [%0], [%1], 16;" :: "r"(dst_u32), "l"(src_ptr))
#define CP_COMMIT()  asm volatile("cp.async.commit_group;" ::: "memory")
#define CP_WAIT(N)   asm volatile("cp.async.wait_group %0;" :: "n"(N) : "memory")

__device__ __forceinline__ uint32_t f2tf32(float f) {
    uint32_t r;
    asm("cvt.rna.tf32.f32 %0, %1;" : "=r"(r) : "f"(f));
    return r;
}
__device__ __forceinline__ void mma_tf32(float* c, const uint32_t* a, const uint32_t* b) {
    asm volatile(
        "mma.sync.aligned.m16n8k8.row.col.f32.tf32.tf32.f32 "
        "{%0,%1,%2,%3}, {%4,%5,%6,%7}, {%8,%9}, {%0,%1,%2,%3};"
        : "+f"(c[0]), "+f"(c[1]), "+f"(c[2]), "+f"(c[3])
        : "r"(a[0]), "r"(a[1]), "r"(a[2]), "r"(a[3]), "r"(b[0]), "r"(b[1]));
}

// ============================================================
// Routing: softmax -> top2 -> renormalize; padded per-expert slot lists (x128).
// ============================================================
__global__ void routing_kernel(const float* __restrict__ logits) {
    __shared__ int s_cnt[N_EXP];
    __shared__ int s_cur[N_EXP];
    __shared__ int s_off[N_EXP + 1];

    const int t = threadIdx.x;
    if (t < N_EXP) { s_cnt[t] = 0; s_cur[t] = 0; }
    for (int s = t; s < MAXSLOT; s += blockDim.x) g_token_of_slot[s] = -1;
    __syncthreads();

    int e1 = 0, e2 = 0;
    float w1 = 0.f, w2 = 0.f;
    if (t < T_TOK) {
        float l[N_EXP];
#pragma unroll
        for (int e = 0; e < N_EXP; e++) l[e] = logits[t * N_EXP + e];
        float b1 = -1e30f;
#pragma unroll
        for (int e = 0; e < N_EXP; e++) if (l[e] > b1) { b1 = l[e]; e1 = e; }
        float b2 = -1e30f;
        e2 = (e1 == 0) ? 1 : 0;
#pragma unroll
        for (int e = 0; e < N_EXP; e++) if (e != e1 && l[e] > b2) { b2 = l[e]; e2 = e; }
        float p2 = expf(b2 - b1);
        w1 = 1.f / (1.f + p2);
        w2 = p2 / (1.f + p2);
        atomicAdd(&s_cnt[e1], 1);
        atomicAdd(&s_cnt[e2], 1);
    }
    __syncthreads();

    if (t == 0) {
        int off = 0;
        for (int e = 0; e < N_EXP; e++) {
            s_off[e] = off;
            int tiles = (s_cnt[e] + BM - 1) / BM;
            for (int i = 0; i < tiles; i++) g_tile_expert[off / BM + i] = e;
            off += tiles * BM;
        }
        s_off[N_EXP] = off;
        g_num_tiles = off / BM;
    }
    __syncthreads();

    if (t < T_TOK) {
        int p = atomicAdd(&s_cur[e1], 1);
        int s = s_off[e1] + p;
        g_token_of_slot[s] = t;
        g_slot_weight[s]   = w1;
        p = atomicAdd(&s_cur[e2], 1);
        s = s_off[e2] + p;
        g_token_of_slot[s] = t;
        g_slot_weight[s]   = w2;
    }
}

// ============================================================
// Fragment context + per-chunk MMA (warp grid 2m x 4n, warp tile 64x32)
// ============================================================
struct FragCtx { int wm, wn, g, tg; };

__device__ __forceinline__ void mma_chunk(const float* __restrict__ A,
                                          const float* __restrict__ B,
                                          const FragCtx& f,
                                          float acc[4][4][4]) {
#pragma unroll
    for (int ks = 0; ks < 4; ks++) {
        uint32_t af[4][4];
#pragma unroll
        for (int mf = 0; mf < 4; mf++) {
            const int row = f.wm * 64 + mf * 16 + f.g;
            const int base = row * SM_STRIDE + ks * 8 + f.tg;
            af[mf][0] = f2tf32(A[base]);
            af[mf][1] = f2tf32(A[base + 8 * SM_STRIDE]);
            af[mf][2] = f2tf32(A[base + 4]);
            af[mf][3] = f2tf32(A[base + 8 * SM_STRIDE + 4]);
        }
        uint32_t bf[4][2];
#pragma unroll
        for (int nf = 0; nf < 4; nf++) {
            const int n = f.wn * 32 + nf * 8 + f.g;
            const int base = n * SM_STRIDE + ks * 8 + f.tg;
            bf[nf][0] = f2tf32(B[base]);
            bf[nf][1] = f2tf32(B[base + 4]);
        }
#pragma unroll
        for (int mf = 0; mf < 4; mf++)
#pragma unroll
            for (int nf = 0; nf < 4; nf++)
                mma_tf32(acc[mf][nf], af[mf], bf[nf]);
    }
}

// issue one chunk's loads for this thread (4x16B A + 4x16B B)
__device__ __forceinline__ void issue_chunk(uint32_t aDst, uint32_t bDst,
                                            const float* aSrc, const float* bSrc,
                                            int kOff, int sb) {
#pragma unroll
    for (int i = 0; i < 4; i++) {
        CP_ASYNC16(aDst + i * 16, aSrc + kOff + (sb + i) * 4);
        CP_ASYNC16(bDst + i * 16, bSrc + kOff + (sb + i) * 4);
    }
    CP_COMMIT();
}

// ============================================================
// GEMM1 + SiLU*up. B rows interleaved gate/up. grid = (MAXTILES, I/64)
// ============================================================
__global__ __launch_bounds__(256)
void gemm1_mma(const float* __restrict__ x, const float* __restrict__ w13) {
    const int tile_m = blockIdx.x;
    if (tile_m >= g_num_tiles) return;
    const int e   = g_tile_expert[tile_m];
    const int nbJ = blockIdx.y * 64;

    extern __shared__ float sm[];

    const int tid = threadIdx.x;
    const int wid = tid >> 5, lid = tid & 31;
    FragCtx f = { wid & 1, wid >> 1, lid >> 2, lid & 3 };

    const int r  = tid >> 1;
    const int sb = (tid & 1) * 4;
    const int tokr = g_token_of_slot[tile_m * BM + r];
    const float* aSrc = x + (size_t)(tokr < 0 ? 0 : tokr) * H_DIM;
    const int j = r >> 1;
    const int wrow = (r & 1) ? (I_DIM + nbJ + j) : (nbJ + j);
    const float* bSrc = w13 + ((size_t)e * 2 * I_DIM + wrow) * H_DIM;

    const uint32_t smBase = smem_u32(sm);
    const uint32_t thrOff = r * (SM_STRIDE * 4) + sb * 16;
    uint32_t aDst[NSTAGE], bDst[NSTAGE];
#pragma unroll
    for (int s = 0; s < NSTAGE; s++) {
        aDst[s] = smBase + s * (TILE_WORDS * 4) + thrOff;
        bDst[s] = smBase + (NSTAGE + s) * (TILE_WORDS * 4) + thrOff;
    }

    float acc[4][4][4];
#pragma unroll
    for (int a = 0; a < 4; a++)
#pragma unroll
        for (int b = 0; b < 4; b++)
#pragma unroll
            for (int c = 0; c < 4; c++) acc[a][b][c] = 0.f;

    const int NC = H_DIM / BK;   // 64
    issue_chunk(aDst[0], bDst[0], aSrc, bSrc, 0, sb);
    issue_chunk(aDst[1], bDst[1], aSrc, bSrc, BK, sb);

    int stage = 0, stage2 = 2;   // stage of chunk c, stage of chunk c+2
#pragma unroll 1
    for (int c = 0; c < NC; c++) {
        if (c + 1 < NC) CP_WAIT(1); else CP_WAIT(0);
        __syncthreads();
        if (c + 2 < NC)
            issue_chunk(aDst[stage2], bDst[stage2], aSrc, bSrc, (c + 2) * BK, sb);
        mma_chunk(sm + stage * TILE_WORDS, sm + (NSTAGE + stage) * TILE_WORDS, f, acc);
        stage = (stage + 1 == NSTAGE) ? 0 : stage + 1;
        stage2 = (stage2 + 1 == NSTAGE) ? 0 : stage2 + 1;
    }

    // epilogue: silu(gate)*up; thread's c-pair (even,odd) = (gate, up) of same col
#pragma unroll
    for (int mf = 0; mf < 4; mf++) {
#pragma unroll
        for (int half = 0; half < 2; half++) {
            const int slot = tile_m * BM + f.wm * 64 + mf * 16 + f.g + half * 8;
            if (g_token_of_slot[slot] >= 0) {
                float* dst = g_act + (size_t)slot * I_DIM + nbJ;
#pragma unroll
                for (int nf = 0; nf < 4; nf++) {
                    const int jj = f.wn * 16 + nf * 4 + f.tg;
                    const float gt = acc[mf][nf][half * 2 + 0];
                    const float up = acc[mf][nf][half * 2 + 1];
                    dst[jj] = up * gt / (1.f + expf(-gt));
                }
            }
        }
    }
}

// ============================================================
// GEMM2 + weighted atomic scatter. grid = (MAXTILES, H/128)
// ============================================================
__global__ __launch_bounds__(256)
void gemm2_mma(const float* __restrict__ w2, float* __restrict__ out) {
    const int tile_m = blockIdx.x;
    if (tile_m >= g_num_tiles) return;
    const int e     = g_tile_expert[tile_m];
    const int nbase = blockIdx.y * BN;

    extern __shared__ float sm[];

    const int tid = threadIdx.x;
    const int wid = tid >> 5, lid = tid & 31;
    FragCtx f = { wid & 1, wid >> 1, lid >> 2, lid & 3 };

    const int r  = tid >> 1;
    const int sb = (tid & 1) * 4;
    const float* aSrc = g_act + (size_t)(tile_m * BM + r) * I_DIM;   // pad rows stay 0
    const float* bSrc = w2 + ((size_t)e * H_DIM + (nbase + r)) * I_DIM;

    const uint32_t smBase = smem_u32(sm);
    const uint32_t thrOff = r * (SM_STRIDE * 4) + sb * 16;
    uint32_t aDst[NSTAGE], bDst[NSTAGE];
#pragma unroll
    for (int s = 0; s < NSTAGE; s++) {
        aDst[s] = smBase + s * (TILE_WORDS * 4) + thrOff;
        bDst[s] = smBase + (NSTAGE + s) * (TILE_WORDS * 4) + thrOff;
    }

    float acc[4][4][4];
#pragma unroll
    for (int a = 0; a < 4; a++)
#pragma unroll
        for (int b = 0; b < 4; b++)
#pragma unroll
            for (int c = 0; c < 4; c++) acc[a][b][c] = 0.f;

    const int NC = I_DIM / BK;   // 44
    issue_chunk(aDst[0], bDst[0], aSrc, bSrc, 0, sb);
    issue_chunk(aDst[1], bDst[1], aSrc, bSrc, BK, sb);

    int stage = 0, stage2 = 2;
#pragma unroll 1
    for (int c = 0; c < NC; c++) {
        if (c + 1 < NC) CP_WAIT(1); else CP_WAIT(0);
        __syncthreads();
        if (c + 2 < NC)
            issue_chunk(aDst[stage2], bDst[stage2], aSrc, bSrc, (c + 2) * BK, sb);
        mma_chunk(sm + stage * TILE_WORDS, sm + (NSTAGE + stage) * TILE_WORDS, f, acc);
        stage = (stage + 1 == NSTAGE) ? 0 : stage + 1;
        stage2 = (stage2 + 1 == NSTAGE) ? 0 : stage2 + 1;
    }

#pragma unroll
    for (int mf = 0; mf < 4; mf++) {
#pragma unroll
        for (int half = 0; half < 2; half++) {
            const int slot = tile_m * BM + f.wm * 64 + mf * 16 + f.g + half * 8;
            const int tok  = g_token_of_slot[slot];
            if (tok >= 0) {
                const float w = g_slot_weight[slot];
                float* dst = out + (size_t)tok * H_DIM + nbase;
#pragma unroll
                for (int nf = 0; nf < 4; nf++) {
                    const int col = f.wn * 32 + nf * 8 + f.tg * 2;
                    atomicAdd(&dst[col],     w * acc[mf][nf][half * 2 + 0]);
                    atomicAdd(&dst[col + 1], w * acc[mf][nf][half * 2 + 1]);
                }
            }
        }
    }
}

// ============================================================
extern "C" void kernel_launch(void* const* d_in, const int* in_sizes, int n_in,
                              void* d_out, int out_size) {
    const float* x      = (const float*)d_in[0];   // [1024, 2048]
    const float* logits = (const float*)d_in[1];   // [1024, 8]
    const float* w13    = (const float*)d_in[2];   // [8, 2816, 2048]
    const float* w2     = (const float*)d_in[3];   // [8, 2048, 1408]
    float* out = (float*)d_out;                    // [1024, 2048]
    (void)in_sizes; (void)n_in;

    cudaFuncSetAttribute(gemm1_mma, cudaFuncAttributeMaxDynamicSharedMemorySize, SMEM_DYN_BYTES);
    cudaFuncSetAttribute(gemm2_mma, cudaFuncAttributeMaxDynamicSharedMemorySize, SMEM_DYN_BYTES);

    cudaMemsetAsync(d_out, 0, (size_t)out_size * sizeof(float));
    routing_kernel<<<1, 1024>>>(logits);
    gemm1_mma<<<dim3(MAXTILES, I_DIM / 64), 256, SMEM_DYN_BYTES>>>(x, w13);
    gemm2_mma<<<dim3(MAXTILES, H_DIM / BN), 256, SMEM_DYN_BYTES>>>(w2, out);
}

// round 7
// speedup vs baseline: 2.3485x; 1.2234x over previous
#include <cuda_runtime.h>
#include <cstdint>
#include <math.h>

// ---------------- problem constants ----------------
#define T_TOK 1024
#define H_DIM 2048
#define I_DIM 1408
#define N_EXP 8

// ---------------- tiling ----------------
#define BM 128
#define BN 128
#define BK 32
#define NSTAGE 3
#define MAXSLOT  3072
#define MAXTILES 24
#define NTHREADS 512

#define SM_STRIDE 36      // floats per smem row (144 B; frag banks (4g+tg)%32 all distinct)
#define TILE_WORDS (BM * SM_STRIDE)                     // 4608 floats = 18 KB
#define SMEM_DYN_BYTES (2 * NSTAGE * TILE_WORDS * 4)    // 3 stages x (A+B) = 108 KB

// ---------------- scratch ----------------
__device__ int   g_token_of_slot[MAXSLOT];
__device__ float g_slot_weight[MAXSLOT];
__device__ int   g_tile_expert[MAXTILES];
__device__ int   g_num_tiles;
__device__ float g_act[(size_t)MAXSLOT * I_DIM];   // ~17.3 MB

// ---------------- PTX helpers (baseline sm_80+; nothing 'a'-gated) ----------------
__device__ __forceinline__ uint32_t smem_u32(const void* p) {
    uint32_t a;
    asm("{ .reg .u64 t; cvta.to.shared.u64 t, %1; cvt.u32.u64 %0, t; }" : "=r"(a) : "l"(p));
    return a;
}
#define CP_ASYNC16(dst_u32, src_ptr) \
    asm volatile("cp.async.cg.shared.global [%0], [%1], 16;" :: "r"(dst_u32), "l"(src_ptr))
#define CP_COMMIT()  asm volatile("cp.async.commit_group;" ::: "memory")
#define CP_WAIT(N)   asm volatile("cp.async.wait_group %0;" :: "n"(N) : "memory")

__device__ __forceinline__ uint32_t f2tf32(float f) {
    uint32_t r;
    asm("cvt.rna.tf32.f32 %0, %1;" : "=r"(r) : "f"(f));
    return r;
}
__device__ __forceinline__ void mma_tf32(float* c, const uint32_t* a, const uint32_t* b) {
    asm volatile(
        "mma.sync.aligned.m16n8k8.row.col.f32.tf32.tf32.f32 "
        "{%0,%1,%2,%3}, {%4,%5,%6,%7}, {%8,%9}, {%0,%1,%2,%3};"
        : "+f"(c[0]), "+f"(c[1]), "+f"(c[2]), "+f"(c[3])
        : "r"(a[0]), "r"(a[1]), "r"(a[2]), "r"(a[3]), "r"(b[0]), "r"(b[1]));
}

// ============================================================
// Routing: softmax -> top2 -> renormalize; padded per-expert slot lists (x128).
// ============================================================
__global__ void routing_kernel(const float* __restrict__ logits) {
    __shared__ int s_cnt[N_EXP];
    __shared__ int s_cur[N_EXP];
    __shared__ int s_off[N_EXP + 1];

    const int t = threadIdx.x;
    if (t < N_EXP) { s_cnt[t] = 0; s_cur[t] = 0; }
    for (int s = t; s < MAXSLOT; s += blockDim.x) g_token_of_slot[s] = -1;
    __syncthreads();

    int e1 = 0, e2 = 0;
    float w1 = 0.f, w2 = 0.f;
    if (t < T_TOK) {
        float l[N_EXP];
#pragma unroll
        for (int e = 0; e < N_EXP; e++) l[e] = logits[t * N_EXP + e];
        float b1 = -1e30f;
#pragma unroll
        for (int e = 0; e < N_EXP; e++) if (l[e] > b1) { b1 = l[e]; e1 = e; }
        float b2 = -1e30f;
        e2 = (e1 == 0) ? 1 : 0;
#pragma unroll
        for (int e = 0; e < N_EXP; e++) if (e != e1 && l[e] > b2) { b2 = l[e]; e2 = e; }
        float p2 = expf(b2 - b1);
        w1 = 1.f / (1.f + p2);
        w2 = p2 / (1.f + p2);
        atomicAdd(&s_cnt[e1], 1);
        atomicAdd(&s_cnt[e2], 1);
    }
    __syncthreads();

    if (t == 0) {
        int off = 0;
        for (int e = 0; e < N_EXP; e++) {
            s_off[e] = off;
            int tiles = (s_cnt[e] + BM - 1) / BM;
            for (int i = 0; i < tiles; i++) g_tile_expert[off / BM + i] = e;
            off += tiles * BM;
        }
        s_off[N_EXP] = off;
        g_num_tiles = off / BM;
    }
    __syncthreads();

    if (t < T_TOK) {
        int p = atomicAdd(&s_cur[e1], 1);
        int s = s_off[e1] + p;
        g_token_of_slot[s] = t;
        g_slot_weight[s]   = w1;
        p = atomicAdd(&s_cur[e2], 1);
        s = s_off[e2] + p;
        g_token_of_slot[s] = t;
        g_slot_weight[s]   = w2;
    }
}

// ============================================================
// Fragment context + per-chunk MMA.
// 16 warps: wm = wid&3 (m-group of 32 rows), wn = wid>>2 (n-group of 32 cols).
// Warp tile 32x32: mf 0..1 (16 rows), nf 0..3 (8 cols). acc[2][4][4].
// ============================================================
struct FragCtx { int wm, wn, g, tg; };

__device__ __forceinline__ void mma_chunk(const float* __restrict__ A,
                                          const float* __restrict__ B,
                                          const FragCtx& f,
                                          float acc[2][4][4]) {
#pragma unroll
    for (int ks = 0; ks < 4; ks++) {
        uint32_t af[2][4];
#pragma unroll
        for (int mf = 0; mf < 2; mf++) {
            const int row = f.wm * 32 + mf * 16 + f.g;
            const int base = row * SM_STRIDE + ks * 8 + f.tg;
            af[mf][0] = f2tf32(A[base]);
            af[mf][1] = f2tf32(A[base + 8 * SM_STRIDE]);
            af[mf][2] = f2tf32(A[base + 4]);
            af[mf][3] = f2tf32(A[base + 8 * SM_STRIDE + 4]);
        }
        uint32_t bf[4][2];
#pragma unroll
        for (int nf = 0; nf < 4; nf++) {
            const int n = f.wn * 32 + nf * 8 + f.g;
            const int base = n * SM_STRIDE + ks * 8 + f.tg;
            bf[nf][0] = f2tf32(B[base]);
            bf[nf][1] = f2tf32(B[base + 4]);
        }
#pragma unroll
        for (int mf = 0; mf < 2; mf++)
#pragma unroll
            for (int nf = 0; nf < 4; nf++)
                mma_tf32(acc[mf][nf], af[mf], bf[nf]);
    }
}

// per-thread loads: 2x16B A + 2x16B B (512 threads cover 128 rows x 8 segs each)
__device__ __forceinline__ void issue_chunk(uint32_t aDst, uint32_t bDst,
                                            const float* aSrc, const float* bSrc,
                                            int kOff, int sb) {
#pragma unroll
    for (int i = 0; i < 2; i++) {
        CP_ASYNC16(aDst + i * 16, aSrc + kOff + (sb + i) * 4);
        CP_ASYNC16(bDst + i * 16, bSrc + kOff + (sb + i) * 4);
    }
    CP_COMMIT();
}

// ============================================================
// GEMM1 + SiLU*up. B rows interleaved gate/up. grid = (MAXTILES, I/64), 512 thr
// ============================================================
__global__ __launch_bounds__(NTHREADS)
void gemm1_mma(const float* __restrict__ x, const float* __restrict__ w13) {
    const int tile_m = blockIdx.x;
    if (tile_m >= g_num_tiles) return;
    const int e   = g_tile_expert[tile_m];
    const int nbJ = blockIdx.y * 64;

    extern __shared__ float sm[];

    const int tid = threadIdx.x;
    const int wid = tid >> 5, lid = tid & 31;
    FragCtx f = { wid & 3, wid >> 2, lid >> 2, lid & 3 };

    const int r  = tid >> 2;            // 0..127
    const int sb = (tid & 3) * 2;       // seg pairs 0,2,4,6
    const int tokr = g_token_of_slot[tile_m * BM + r];
    const float* aSrc = x + (size_t)(tokr < 0 ? 0 : tokr) * H_DIM;
    const int j = r >> 1;
    const int wrow = (r & 1) ? (I_DIM + nbJ + j) : (nbJ + j);
    const float* bSrc = w13 + ((size_t)e * 2 * I_DIM + wrow) * H_DIM;

    const uint32_t smBase = smem_u32(sm);
    const uint32_t thrOff = r * (SM_STRIDE * 4) + sb * 16;
    uint32_t aDst[NSTAGE], bDst[NSTAGE];
#pragma unroll
    for (int s = 0; s < NSTAGE; s++) {
        aDst[s] = smBase + s * (TILE_WORDS * 4) + thrOff;
        bDst[s] = smBase + (NSTAGE + s) * (TILE_WORDS * 4) + thrOff;
    }

    float acc[2][4][4];
#pragma unroll
    for (int a = 0; a < 2; a++)
#pragma unroll
        for (int b = 0; b < 4; b++)
#pragma unroll
            for (int c = 0; c < 4; c++) acc[a][b][c] = 0.f;

    const int NC = H_DIM / BK;   // 64
    issue_chunk(aDst[0], bDst[0], aSrc, bSrc, 0, sb);
    issue_chunk(aDst[1], bDst[1], aSrc, bSrc, BK, sb);

    int stage = 0, stage2 = 2;
#pragma unroll 1
    for (int c = 0; c < NC; c++) {
        if (c + 1 < NC) CP_WAIT(1); else CP_WAIT(0);
        __syncthreads();
        if (c + 2 < NC)
            issue_chunk(aDst[stage2], bDst[stage2], aSrc, bSrc, (c + 2) * BK, sb);
        mma_chunk(sm + stage * TILE_WORDS, sm + (NSTAGE + stage) * TILE_WORDS, f, acc);
        stage = (stage + 1 == NSTAGE) ? 0 : stage + 1;
        stage2 = (stage2 + 1 == NSTAGE) ? 0 : stage2 + 1;
    }

    // epilogue: silu(gate)*up; c-pair (even,odd) = (gate, up) of same col
#pragma unroll
    for (int mf = 0; mf < 2; mf++) {
#pragma unroll
        for (int half = 0; half < 2; half++) {
            const int slot = tile_m * BM + f.wm * 32 + mf * 16 + f.g + half * 8;
            if (g_token_of_slot[slot] >= 0) {
                float* dst = g_act + (size_t)slot * I_DIM + nbJ;
#pragma unroll
                for (int nf = 0; nf < 4; nf++) {
                    const int jj = f.wn * 16 + nf * 4 + f.tg;
                    const float gt = acc[mf][nf][half * 2 + 0];
                    const float up = acc[mf][nf][half * 2 + 1];
                    dst[jj] = up * gt / (1.f + expf(-gt));
                }
            }
        }
    }
}

// ============================================================
// GEMM2 + weighted atomic scatter. grid = (MAXTILES, H/128), 512 thr
// ============================================================
__global__ __launch_bounds__(NTHREADS)
void gemm2_mma(const float* __restrict__ w2, float* __restrict__ out) {
    const int tile_m = blockIdx.x;
    if (tile_m >= g_num_tiles) return;
    const int e     = g_tile_expert[tile_m];
    const int nbase = blockIdx.y * BN;

    extern __shared__ float sm[];

    const int tid = threadIdx.x;
    const int wid = tid >> 5, lid = tid & 31;
    FragCtx f = { wid & 3, wid >> 2, lid >> 2, lid & 3 };

    const int r  = tid >> 2;
    const int sb = (tid & 3) * 2;
    const float* aSrc = g_act + (size_t)(tile_m * BM + r) * I_DIM;   // pad rows stay 0
    const float* bSrc = w2 + ((size_t)e * H_DIM + (nbase + r)) * I_DIM;

    const uint32_t smBase = smem_u32(sm);
    const uint32_t thrOff = r * (SM_STRIDE * 4) + sb * 16;
    uint32_t aDst[NSTAGE], bDst[NSTAGE];
#pragma unroll
    for (int s = 0; s < NSTAGE; s++) {
        aDst[s] = smBase + s * (TILE_WORDS * 4) + thrOff;
        bDst[s] = smBase + (NSTAGE + s) * (TILE_WORDS * 4) + thrOff;
    }

    float acc[2][4][4];
#pragma unroll
    for (int a = 0; a < 2; a++)
#pragma unroll
        for (int b = 0; b < 4; b++)
#pragma unroll
            for (int c = 0; c < 4; c++) acc[a][b][c] = 0.f;

    const int NC = I_DIM / BK;   // 44
    issue_chunk(aDst[0], bDst[0], aSrc, bSrc, 0, sb);
    issue_chunk(aDst[1], bDst[1], aSrc, bSrc, BK, sb);

    int stage = 0, stage2 = 2;
#pragma unroll 1
    for (int c = 0; c < NC; c++) {
        if (c + 1 < NC) CP_WAIT(1); else CP_WAIT(0);
        __syncthreads();
        if (c + 2 < NC)
            issue_chunk(aDst[stage2], bDst[stage2], aSrc, bSrc, (c + 2) * BK, sb);
        mma_chunk(sm + stage * TILE_WORDS, sm + (NSTAGE + stage) * TILE_WORDS, f, acc);
        stage = (stage + 1 == NSTAGE) ? 0 : stage + 1;
        stage2 = (stage2 + 1 == NSTAGE) ? 0 : stage2 + 1;
    }

#pragma unroll
    for (int mf = 0; mf < 2; mf++) {
#pragma unroll
        for (int half = 0; half < 2; half++) {
            const int slot = tile_m * BM + f.wm * 32 + mf * 16 + f.g + half * 8;
            const int tok  = g_token_of_slot[slot];
            if (tok >= 0) {
                const float w = g_slot_weight[slot];
                float* dst = out + (size_t)tok * H_DIM + nbase;
#pragma unroll
                for (int nf = 0; nf < 4; nf++) {
                    const int col = f.wn * 32 + nf * 8 + f.tg * 2;
                    atomicAdd(&dst[col],     w * acc[mf][nf][half * 2 + 0]);
                    atomicAdd(&dst[col + 1], w * acc[mf][nf][half * 2 + 1]);
                }
            }
        }
    }
}

// ============================================================
extern "C" void kernel_launch(void* const* d_in, const int* in_sizes, int n_in,
                              void* d_out, int out_size) {
    const float* x      = (const float*)d_in[0];   // [1024, 2048]
    const float* logits = (const float*)d_in[1];   // [1024, 8]
    const float* w13    = (const float*)d_in[2];   // [8, 2816, 2048]
    const float* w2     = (const float*)d_in[3];   // [8, 2048, 1408]
    float* out = (float*)d_out;                    // [1024, 2048]
    (void)in_sizes; (void)n_in;

    cudaFuncSetAttribute(gemm1_mma, cudaFuncAttributeMaxDynamicSharedMemorySize, SMEM_DYN_BYTES);
    cudaFuncSetAttribute(gemm2_mma, cudaFuncAttributeMaxDynamicSharedMemorySize, SMEM_DYN_BYTES);

    cudaMemsetAsync(d_out, 0, (size_t)out_size * sizeof(float));
    routing_kernel<<<1, 1024>>>(logits);
    gemm1_mma<<<dim3(MAXTILES, I_DIM / 64), NTHREADS, SMEM_DYN_BYTES>>>(x, w13);
    gemm2_mma<<<dim3(MAXTILES, H_DIM / BN), NTHREADS, SMEM_DYN_BYTES>>>(w2, out);
}